// round 1
// baseline (speedup 1.0000x reference)
#include <cuda_runtime.h>

#define N_NODES 100000
#define N_EDGES 3200000
#define D_FEAT  512

// Scratch (no device allocation allowed — use __device__ globals)
__device__ float g_deg[N_NODES];
__device__ float g_h[N_NODES];     // h = x@W, later overwritten with hn = h*dinv
__device__ float g_dinv[N_NODES];

// K1: deg starts at 1.0 (self-loop edge weight)
__global__ void k_init() {
    int i = blockIdx.x * blockDim.x + threadIdx.x;
    if (i < N_NODES) g_deg[i] = 1.0f;
}

// K2: degree of destination nodes over A (self-loop already in init)
__global__ void k_deg(const int* __restrict__ dst) {
    int e = blockIdx.x * blockDim.x + threadIdx.x;   // 1 int4 per thread
    if (e < N_EDGES / 4) {
        int4 d = ((const int4*)dst)[e];
        atomicAdd(&g_deg[d.x], 1.0f);
        atomicAdd(&g_deg[d.y], 1.0f);
        atomicAdd(&g_deg[d.z], 1.0f);
        atomicAdd(&g_deg[d.w], 1.0f);
    }
}

// K3: h[i] = dot(x[i,:], W)  — warp per node, float4 coalesced loads
__global__ void k_h(const float* __restrict__ x, const float* __restrict__ W) {
    __shared__ float sW[D_FEAT];
    for (int i = threadIdx.x; i < D_FEAT; i += blockDim.x) sW[i] = W[i];
    __syncthreads();

    int gwarp = (blockIdx.x * blockDim.x + threadIdx.x) >> 5;  // node id
    int lane  = threadIdx.x & 31;
    if (gwarp >= N_NODES) return;

    const float4* xr = (const float4*)(x + (size_t)gwarp * D_FEAT);
    const float4* wr = (const float4*)sW;
    float acc = 0.0f;
    #pragma unroll
    for (int i = 0; i < 4; i++) {
        int idx = lane + i * 32;          // 128 float4 per row
        float4 v = xr[idx];
        float4 w = wr[idx];
        acc += v.x * w.x + v.y * w.y + v.z * w.z + v.w * w.w;
    }
    #pragma unroll
    for (int o = 16; o > 0; o >>= 1)
        acc += __shfl_xor_sync(0xffffffffu, acc, o);
    if (lane == 0) g_h[gwarp] = acc;
}

// K4: dinv = rsqrt(deg); out = self-loop term; hn = h*dinv (in place)
__global__ void k_comb(float* __restrict__ out) {
    int i = blockIdx.x * blockDim.x + threadIdx.x;
    if (i < N_NODES) {
        float d = rsqrtf(g_deg[i]);       // deg >= 1 always (self-loop)
        g_dinv[i] = d;
        float h = g_h[i];
        g_h[i]  = h * d;                  // hn[src] term for edge kernel
        out[i]  = h * d * d;              // self-loop: norm = dinv[i]^2
    }
}

// K5: out[dst] += hn[src] * dinv[dst]
__global__ void k_edge(const int* __restrict__ src, const int* __restrict__ dst,
                       float* __restrict__ out) {
    int e = blockIdx.x * blockDim.x + threadIdx.x;   // 1 int4 per thread
    if (e < N_EDGES / 4) {
        int4 s = ((const int4*)src)[e];
        int4 d = ((const int4*)dst)[e];
        atomicAdd(&out[d.x], g_h[s.x] * g_dinv[d.x]);
        atomicAdd(&out[d.y], g_h[s.y] * g_dinv[d.y]);
        atomicAdd(&out[d.z], g_h[s.z] * g_dinv[d.z]);
        atomicAdd(&out[d.w], g_h[s.w] * g_dinv[d.w]);
    }
}

extern "C" void kernel_launch(void* const* d_in, const int* in_sizes, int n_in,
                              void* d_out, int out_size) {
    const float* x    = (const float*)d_in[0];            // [N_NODES, D_FEAT]
    const int*   eidx = (const int*)d_in[1];              // [2, N_EDGES] row-major
    const float* W    = (const float*)d_in[2];            // [D_FEAT, 1]
    float* out        = (float*)d_out;                    // [N_NODES]

    const int* src = eidx;                // row 0
    const int* dst = eidx + N_EDGES;      // row 1

    const int T = 256;
    // K1: init deg
    k_init<<<(N_NODES + T - 1) / T, T>>>();
    // K2: degree atomics (800k int4 items)
    k_deg<<<(N_EDGES / 4 + T - 1) / T, T>>>(dst);
    // K3: h = x @ W  (100k warps = 12500 blocks x 8 warps)
    k_h<<<N_NODES / 8, T>>>(x, W);
    // K4: dinv / hn / self-loop term
    k_comb<<<(N_NODES + T - 1) / T, T>>>(out);
    // K5: edge scatter
    k_edge<<<(N_EDGES / 4 + T - 1) / T, T>>>(src, dst, out);
}

// round 4
// speedup vs baseline: 1.2935x; 1.2935x over previous
#include <cuda_runtime.h>

#define N_NODES 100000
#define N_EDGES 3200000
#define D_FEAT  512

#define DEG_BLOCKS 3125          // N_EDGES/4 threads @256 = 3125 blocks
#define H_BLOCKS   12500         // N_NODES warps, 8 warps/block
#define T          256

// Scratch (device allocation forbidden). g_deg is zero at module load; k_comb
// resets it to zero after consuming it, so every call sees identical state.
__device__ float g_deg[N_NODES];
__device__ float g_h[N_NODES];     // h = x@W, overwritten with hn = h*dinv
__device__ float g_dinv[N_NODES];

// Fused kernel: 15625 blocks. Every 5th block (bid%5==0, 3125 total) counts
// destination degrees (LTS-atomic-bound); the other 12500 compute h = x @ W
// (DRAM-bound). Interleaving the roles keeps every scheduling wave ~80%
// DRAM-streaming so the atomic traffic hides under the 204.8MB x stream.
__global__ void k_fused(const int* __restrict__ dst,
                        const float* __restrict__ x,
                        const float* __restrict__ W) {
    if (blockIdx.x % 5 == 0) {
        int db = blockIdx.x / 5;                         // 0..3124
        int e  = db * blockDim.x + threadIdx.x;          // 1 int4 per thread
        if (e < N_EDGES / 4) {
            int4 d = ((const int4*)dst)[e];
            atomicAdd(&g_deg[d.x], 1.0f);
            atomicAdd(&g_deg[d.y], 1.0f);
            atomicAdd(&g_deg[d.z], 1.0f);
            atomicAdd(&g_deg[d.w], 1.0f);
        }
    } else {
        __shared__ float sW[D_FEAT];
        for (int i = threadIdx.x; i < D_FEAT; i += blockDim.x) sW[i] = W[i];
        __syncthreads();

        int hb   = blockIdx.x - blockIdx.x / 5 - 1;      // 0..12499
        int node = hb * 8 + (threadIdx.x >> 5);
        int lane = threadIdx.x & 31;
        if (node >= N_NODES) return;

        const float4* xr = (const float4*)(x + (size_t)node * D_FEAT);
        const float4* wr = (const float4*)sW;
        float acc = 0.0f;
        #pragma unroll
        for (int i = 0; i < 4; i++) {
            int idx = lane + i * 32;          // 128 float4 per row
            float4 v = xr[idx];
            float4 w = wr[idx];
            acc += v.x * w.x + v.y * w.y + v.z * w.z + v.w * w.w;
        }
        #pragma unroll
        for (int o = 16; o > 0; o >>= 1)
            acc += __shfl_xor_sync(0xffffffffu, acc, o);
        if (lane == 0) g_h[node] = acc;
    }
}

// dinv = rsqrt(deg + 1 self-loop); hn = h*dinv; out initialized with the
// self-loop term hn[i] (k_final multiplies by dinv[i]); g_deg reset to 0 so
// the next call starts from a clean state (determinism under graph replay).
__global__ void k_comb(float* __restrict__ out) {
    int i = blockIdx.x * blockDim.x + threadIdx.x;
    if (i < N_NODES) {
        float d = rsqrtf(g_deg[i] + 1.0f);
        g_deg[i]  = 0.0f;                 // restore invariant for next call
        g_dinv[i] = d;
        float hn  = g_h[i] * d;
        g_h[i]  = hn;
        out[i]  = hn;                     // self-loop contribution (pre-dinv)
    }
}

// out[dst] += hn[src]   (dinv[dst] factored out of the sum)
__global__ void k_edge(const int* __restrict__ src, const int* __restrict__ dst,
                       float* __restrict__ out) {
    int e = blockIdx.x * blockDim.x + threadIdx.x;   // 1 int4 per thread
    if (e < N_EDGES / 4) {
        int4 s = ((const int4*)src)[e];
        int4 d = ((const int4*)dst)[e];
        atomicAdd(&out[d.x], g_h[s.x]);
        atomicAdd(&out[d.y], g_h[s.y]);
        atomicAdd(&out[d.z], g_h[s.z]);
        atomicAdd(&out[d.w], g_h[s.w]);
    }
}

// out[i] = dinv[i] * (hn[i] + sum of incoming hn)
__global__ void k_final(float* __restrict__ out) {
    int i = blockIdx.x * blockDim.x + threadIdx.x;
    if (i < N_NODES) out[i] *= g_dinv[i];
}

extern "C" void kernel_launch(void* const* d_in, const int* in_sizes, int n_in,
                              void* d_out, int out_size) {
    const float* x    = (const float*)d_in[0];            // [N_NODES, D_FEAT]
    const int*   eidx = (const int*)d_in[1];              // [2, N_EDGES]
    const float* W    = (const float*)d_in[2];            // [D_FEAT, 1]
    float* out        = (float*)d_out;                    // [N_NODES]

    const int* src = eidx;                // row 0
    const int* dst = eidx + N_EDGES;      // row 1

    k_fused<<<DEG_BLOCKS + H_BLOCKS, T>>>(dst, x, W);
    k_comb <<<(N_NODES + T - 1) / T, T>>>(out);
    k_edge <<<(N_EDGES / 4 + T - 1) / T, T>>>(src, dst, out);
    k_final<<<(N_NODES + T - 1) / T, T>>>(out);
}